// round 2
// baseline (speedup 1.0000x reference)
#include <cuda_runtime.h>
#include <cstdint>

// ---------------- problem constants ----------------
#define BS     16384
#define MSEG   6
#define DM     512          // N_HEAD * D_K = 8*64
#define NH     8
#define DHEAD  64
#define DIN    6144
#define NROWS  (BS*MSEG)            // 98304
#define QKV_ELEMS (NROWS*DM)        // 50331648
#define NLOGITS (BS*NH*36)          // 4718592
#define INV_TEMP 0.125f
#define LN_EPS 1e-6f

// ---------------- scratch (device globals; no allocation allowed) ----------------
__device__ float g_Q[QKV_ELEMS];
__device__ float g_K[QKV_ELEMS];
__device__ float g_V[QKV_ELEMS];
__device__ float g_AO[QKV_ELEMS];
__device__ float g_logits[NLOGITS];
__device__ unsigned g_min_bits;

__constant__ int c_segK[6]   = {2048,1024,512,1536,768,256};
__constant__ int c_segOff[6] = {0,2048,3072,3584,5120,5888};

struct WPtrs { const float* w[18]; };   // [seg*3 + {q,k,v}]

// ordered-uint encoding for float atomicMin
__device__ __forceinline__ unsigned fenc(float f) {
    unsigned u = __float_as_uint(f);
    return (u & 0x80000000u) ? ~u : (u | 0x80000000u);
}
__device__ __forceinline__ float fdec(unsigned e) {
    unsigned u = (e & 0x80000000u) ? (e & 0x7fffffffu) : ~e;
    return __uint_as_float(u);
}

// ---------------- K0: init global min ----------------
__global__ void init_min_kernel() { g_min_bits = 0xFFFFFFFFu; }

// ---------------- K1: fused QKV projection GEMM ----------------
// Per segment s: C = data_s (16384 x K_s) @ W^T, W in {wq,wk,wv}, 512 rows each.
// Tile: 128x128, Kchunk 16, 256 threads, 8x8 microtile.
__global__ void __launch_bounds__(256)
qkv_gemm_kernel(const float* __restrict__ inp, WPtrs P)
{
    const int s    = blockIdx.z;
    const int Kdim = c_segK[s];
    const int off  = c_segOff[s];
    const int n0   = blockIdx.x * 128;      // 0..1535
    const int m0   = blockIdx.y * 128;
    const int which = n0 >> 9;              // 0=q 1=k 2=v
    const int nn0   = n0 & 511;
    const float* __restrict__ W = P.w[s*3 + which];
    float* Cbase = (which == 0) ? g_Q : (which == 1) ? g_K : g_V;

    __shared__ float As[16][128];
    __shared__ float Bs[16][128];

    const int tid = threadIdx.x;
    const int tx  = tid & 15;     // n dir
    const int ty  = tid >> 4;     // m dir
    const int lr  = tid >> 2;     // 0..63
    const int lc  = (tid & 3) * 4;

    float acc[8][8];
#pragma unroll
    for (int i = 0; i < 8; i++)
#pragma unroll
        for (int j = 0; j < 8; j++) acc[i][j] = 0.0f;

    const float* Abase = inp + (size_t)m0 * DIN + off;
    const float* Bbase = W + (size_t)nn0 * Kdim;

    for (int k0 = 0; k0 < Kdim; k0 += 16) {
#pragma unroll
        for (int h = 0; h < 2; h++) {
            int r = lr + h * 64;
            float4 a = *(const float4*)(Abase + (size_t)r * DIN + k0 + lc);
            As[lc+0][r] = a.x; As[lc+1][r] = a.y; As[lc+2][r] = a.z; As[lc+3][r] = a.w;
            float4 b = *(const float4*)(Bbase + (size_t)r * Kdim + k0 + lc);
            Bs[lc+0][r] = b.x; Bs[lc+1][r] = b.y; Bs[lc+2][r] = b.z; Bs[lc+3][r] = b.w;
        }
        __syncthreads();
#pragma unroll
        for (int kk = 0; kk < 16; kk++) {
            float a[8], b[8];
            *(float4*)&a[0] = *(const float4*)&As[kk][ty*8];
            *(float4*)&a[4] = *(const float4*)&As[kk][ty*8 + 4];
            *(float4*)&b[0] = *(const float4*)&Bs[kk][tx*8];
            *(float4*)&b[4] = *(const float4*)&Bs[kk][tx*8 + 4];
#pragma unroll
            for (int i = 0; i < 8; i++)
#pragma unroll
                for (int j = 0; j < 8; j++) acc[i][j] += a[i] * b[j];
        }
        __syncthreads();
    }

    // write: C[m, nn0+n] -> buf[(m*6 + s)*512 + nn0 + n]
#pragma unroll
    for (int i = 0; i < 8; i++) {
        int m = m0 + ty * 8 + i;
        size_t rowbase = ((size_t)m * MSEG + s) * DM + nn0;
#pragma unroll
        for (int j = 0; j < 8; j += 4) {
            int n = tx * 8 + j;
            float4 v = make_float4(acc[i][j], acc[i][j+1], acc[i][j+2], acc[i][j+3]);
            *(float4*)(Cbase + rowbase + n) = v;
        }
    }
}

// ---------------- K2: attention logits + global min ----------------
// block = 256 threads = 8 warps, one warp per head; grid = BS
__global__ void __launch_bounds__(256)
attn_logits_kernel()
{
    const int b    = blockIdx.x;
    const int h    = threadIdx.x >> 5;
    const int lane = threadIdx.x & 31;

    const float* Qb = g_Q + (size_t)b * (MSEG*DM) + h * DHEAD + lane;
    const float* Kb = g_K + (size_t)b * (MSEG*DM) + h * DHEAD + lane;

    float q0[6], q1[6], k0v[6], k1v[6];
#pragma unroll
    for (int t = 0; t < 6; t++) {
        q0[t]  = Qb[t*DM];  q1[t]  = Qb[t*DM + 32];
        k0v[t] = Kb[t*DM];  k1v[t] = Kb[t*DM + 32];
    }

    float lmin = 3.4e38f;
    float* lp = g_logits + ((size_t)b * NH + h) * 36;
#pragma unroll
    for (int tq = 0; tq < 6; tq++) {
#pragma unroll
        for (int tk = 0; tk < 6; tk++) {
            float p = q0[tq]*k0v[tk] + q1[tq]*k1v[tk];
#pragma unroll
            for (int o = 16; o > 0; o >>= 1)
                p += __shfl_xor_sync(0xffffffffu, p, o);
            p *= INV_TEMP;
            if (lane == 0) {
                lp[tq*6 + tk] = p;
                lmin = fminf(lmin, p);
            }
        }
    }
    if (lane == 0) atomicMin(&g_min_bits, fenc(lmin));
}

// ---------------- K3: finalize attention (scale/norm/softmax) + attn@V ----------------
// block = 256 threads, grid = BS
__global__ void __launch_bounds__(256)
attn_finalize_kernel(float* __restrict__ attn_out)
{
    const int b   = blockIdx.x;
    const int tid = threadIdx.x;
    __shared__ float at[NH*36];
    __shared__ float s_scale;

    if (tid == 0) s_scale = 1.0f / fabsf(fdec(g_min_bits));
    __syncthreads();
    const float scale = s_scale;

    if (tid < 48) {
        int h = tid / 6, tq = tid % 6;
        const float* lp = g_logits + ((size_t)b * NH + h) * 36 + tq * 6;
        float v[6]; float ss = 0.0f;
#pragma unroll
        for (int k = 0; k < 6; k++) { v[k] = lp[k] * scale; ss += v[k]*v[k]; }
        float inorm = 1.0f / fmaxf(sqrtf(ss), 1e-12f);
        float mx = -3.4e38f;
#pragma unroll
        for (int k = 0; k < 6; k++) { v[k] *= inorm; mx = fmaxf(mx, v[k]); }
        float es = 0.0f; float e[6];
#pragma unroll
        for (int k = 0; k < 6; k++) { e[k] = expf(v[k] - mx); es += e[k]; }
        float r = 1.0f / es;
        float* ao = attn_out + ((size_t)b * NH + h) * 36 + tq * 6;
#pragma unroll
        for (int k = 0; k < 6; k++) {
            float a = e[k] * r;
            at[h*36 + tq*6 + k] = a;
            ao[k] = a;
        }
    }
    __syncthreads();

    // AO[b,t,f] = sum_k attn[h,t,k] * V[b,k,f],  f = h*64+d
    const float* Vb  = g_V  + (size_t)b * (MSEG*DM);
    float*       AOb = g_AO + (size_t)b * (MSEG*DM);
    for (int idx = tid; idx < MSEG*DM; idx += 256) {
        int t = idx >> 9;
        int f = idx & 511;
        int h = f >> 6;
        const float* ar = &at[h*36 + t*6];
        float s = 0.0f;
#pragma unroll
        for (int k = 0; k < 6; k++) s += ar[k] * Vb[k*DM + f];
        AOb[idx] = s;
    }
}

// ---------------- K4a: FC GEMM + bias + residual ----------------
// C = AO(98304x512) @ fc_w^T + fc_b + V  -> d_out (out region)
__global__ void __launch_bounds__(256)
fc_gemm_kernel(const float* __restrict__ fc_w, const float* __restrict__ fc_b,
               float* __restrict__ outp)
{
    const int n0 = blockIdx.x * 128;
    const int m0 = blockIdx.y * 128;

    __shared__ float As[16][128];
    __shared__ float Bs[16][128];

    const int tid = threadIdx.x;
    const int tx  = tid & 15;
    const int ty  = tid >> 4;
    const int lr  = tid >> 2;
    const int lc  = (tid & 3) * 4;

    float acc[8][8];
#pragma unroll
    for (int i = 0; i < 8; i++)
#pragma unroll
        for (int j = 0; j < 8; j++) acc[i][j] = 0.0f;

    const float* Abase = g_AO + (size_t)m0 * DM;
    const float* Bbase = fc_w + (size_t)n0 * DM;

    for (int k0 = 0; k0 < DM; k0 += 16) {
#pragma unroll
        for (int h = 0; h < 2; h++) {
            int r = lr + h * 64;
            float4 a = *(const float4*)(Abase + (size_t)r * DM + k0 + lc);
            As[lc+0][r] = a.x; As[lc+1][r] = a.y; As[lc+2][r] = a.z; As[lc+3][r] = a.w;
            float4 bb = *(const float4*)(Bbase + (size_t)r * DM + k0 + lc);
            Bs[lc+0][r] = bb.x; Bs[lc+1][r] = bb.y; Bs[lc+2][r] = bb.z; Bs[lc+3][r] = bb.w;
        }
        __syncthreads();
#pragma unroll
        for (int kk = 0; kk < 16; kk++) {
            float a[8], b[8];
            *(float4*)&a[0] = *(const float4*)&As[kk][ty*8];
            *(float4*)&a[4] = *(const float4*)&As[kk][ty*8 + 4];
            *(float4*)&b[0] = *(const float4*)&Bs[kk][tx*8];
            *(float4*)&b[4] = *(const float4*)&Bs[kk][tx*8 + 4];
#pragma unroll
            for (int i = 0; i < 8; i++)
#pragma unroll
                for (int j = 0; j < 8; j++) acc[i][j] += a[i] * b[j];
        }
        __syncthreads();
    }

#pragma unroll
    for (int i = 0; i < 8; i++) {
        int m = m0 + ty * 8 + i;
        size_t rowbase = (size_t)m * DM;
#pragma unroll
        for (int j = 0; j < 8; j++) {
            int n = n0 + tx * 8 + j;
            acc[i][j] += fc_b[n] + g_V[rowbase + n];
        }
#pragma unroll
        for (int j = 0; j < 8; j += 4) {
            int n = n0 + tx * 8 + j;
            float4 v = make_float4(acc[i][j], acc[i][j+1], acc[i][j+2], acc[i][j+3]);
            *(float4*)(outp + rowbase + n) = v;
        }
    }
}

// ---------------- K4b: LayerNorm (in-place on d_out out region) ----------------
__global__ void __launch_bounds__(128)
ln_kernel(float* __restrict__ outp, const float* __restrict__ g,
          const float* __restrict__ be)
{
    const int row = blockIdx.x;
    float* p = outp + (size_t)row * DM;
    const int tid = threadIdx.x;

    float4 x = *(const float4*)(p + tid * 4);
    float s  = x.x + x.y + x.z + x.w;
    float sq = x.x*x.x + x.y*x.y + x.z*x.z + x.w*x.w;

#pragma unroll
    for (int o = 16; o > 0; o >>= 1) {
        s  += __shfl_xor_sync(0xffffffffu, s,  o);
        sq += __shfl_xor_sync(0xffffffffu, sq, o);
    }
    __shared__ float ws[4], wq[4];
    int w = tid >> 5, lane = tid & 31;
    if (lane == 0) { ws[w] = s; wq[w] = sq; }
    __syncthreads();
    s  = ws[0] + ws[1] + ws[2] + ws[3];
    sq = wq[0] + wq[1] + wq[2] + wq[3];

    float mu  = s * (1.0f / DM);
    float var = sq * (1.0f / DM) - mu * mu;
    float rstd = rsqrtf(var + LN_EPS);

    int c = tid * 4;
    float4 gg = *(const float4*)(g + c);
    float4 bb = *(const float4*)(be + c);
    float4 o;
    o.x = (x.x - mu) * rstd * gg.x + bb.x;
    o.y = (x.y - mu) * rstd * gg.y + bb.y;
    o.z = (x.z - mu) * rstd * gg.z + bb.z;
    o.w = (x.w - mu) * rstd * gg.w + bb.w;
    *(float4*)(p + c) = o;
}

// ---------------- launch ----------------
extern "C" void kernel_launch(void* const* d_in, const int* in_sizes, int n_in,
                              void* d_out, int out_size)
{
    const float* inp = (const float*)d_in[0];
    WPtrs P;
    for (int i = 0; i < 18; i++) P.w[i] = (const float*)d_in[1 + i];
    const float* fc_w = (const float*)d_in[19];
    const float* fc_b = (const float*)d_in[20];
    const float* ln_g = (const float*)d_in[21];
    const float* ln_b = (const float*)d_in[22];

    float* outp     = (float*)d_out;                     // (16384, 6, 512)
    float* attn_out = outp + (size_t)NROWS * DM;         // (16384, 8, 6, 6)

    init_min_kernel<<<1, 1>>>();
    qkv_gemm_kernel<<<dim3(12, 128, 6), 256>>>(inp, P);
    attn_logits_kernel<<<BS, 256>>>();
    attn_finalize_kernel<<<BS, 256>>>(attn_out);
    fc_gemm_kernel<<<dim3(4, 768), 256>>>(fc_w, fc_b, outp);
    ln_kernel<<<NROWS, 128>>>(outp, ln_g, ln_b);
}

// round 7
// speedup vs baseline: 1.3346x; 1.3346x over previous
#include <cuda_runtime.h>
#include <cuda_bf16.h>
#include <cstdint>

// ---------------- problem constants ----------------
#define BS     16384
#define MSEG   6
#define DM     512
#define NH     8
#define DIN    6144
#define NROWS  (BS*MSEG)            // 98304
#define QKV_ELEMS (NROWS*DM)        // 50331648
#define NLOGITS (BS*NH*36)
#define INV_TEMP 0.125f
#define LN_EPS 1e-6f
#define WPACK  9437184              // 512*6144*3

// ---------------- scratch ----------------
__device__ float g_Q[QKV_ELEMS];
__device__ float g_K[QKV_ELEMS];
__device__ float g_V[QKV_ELEMS];
__device__ float g_logits[NLOGITS];
__device__ unsigned g_min_bits;
__device__ __nv_bfloat16 g_Ah[(size_t)BS*DIN];
__device__ __nv_bfloat16 g_Al[(size_t)BS*DIN];
__device__ __nv_bfloat16 g_Wh[WPACK];
__device__ __nv_bfloat16 g_Wl[WPACK];
__device__ __nv_bfloat16 g_FWh[DM*DM];
__device__ __nv_bfloat16 g_FWl[DM*DM];
__device__ __nv_bfloat16 g_AOh[QKV_ELEMS];
__device__ __nv_bfloat16 g_AOl[QKV_ELEMS];

// combo c = s*3 + w  (w: 0=q, 1=k, 2=v)
__constant__ int c_cK[18]   = {2048,2048,2048,1024,1024,1024,512,512,512,
                               1536,1536,1536,768,768,768,256,256,256};
__constant__ int c_cOff[18] = {0,0,0,2048,2048,2048,3072,3072,3072,
                               3584,3584,3584,5120,5120,5120,5888,5888,5888};
__constant__ int c_cW[18]   = {0,1048576,2097152,3145728,3670016,4194304,
                               4718592,4980736,5242880,5505024,6291456,7077888,
                               7864320,8257536,8650752,9043968,9175040,9306112};

struct WPtrs { const float* w[18]; };

// ---------------- helpers ----------------
__device__ __forceinline__ uint32_t smem_u32(const void* p) {
    uint32_t a;
    asm("{ .reg .u64 t; cvta.to.shared.u64 t, %1; cvt.u32.u64 %0, t; }" : "=r"(a) : "l"(p));
    return a;
}
__device__ __forceinline__ void cpa16(uint32_t s, const void* g) {
    asm volatile("cp.async.cg.shared.global [%0], [%1], 16;" :: "r"(s), "l"(g));
}
__device__ __forceinline__ void cpa_commit() { asm volatile("cp.async.commit_group;" ::: "memory"); }
__device__ __forceinline__ void cpa_wait0()  { asm volatile("cp.async.wait_group 0;" ::: "memory"); }
__device__ __forceinline__ void cpa_wait1()  { asm volatile("cp.async.wait_group 1;" ::: "memory"); }

__device__ __forceinline__ void mma16816(float* c, const uint32_t* a, const uint32_t* b) {
    asm volatile(
        "mma.sync.aligned.m16n8k16.row.col.f32.bf16.bf16.f32 "
        "{%0,%1,%2,%3}, {%4,%5,%6,%7}, {%8,%9}, {%0,%1,%2,%3};"
        : "+f"(c[0]), "+f"(c[1]), "+f"(c[2]), "+f"(c[3])
        : "r"(a[0]), "r"(a[1]), "r"(a[2]), "r"(a[3]), "r"(b[0]), "r"(b[1]));
}

// ---------------- min encoding ----------------
__device__ __forceinline__ unsigned fenc(float f) {
    unsigned u = __float_as_uint(f);
    return (u & 0x80000000u) ? ~u : (u | 0x80000000u);
}
__device__ __forceinline__ float fdec(unsigned e) {
    unsigned u = (e & 0x80000000u) ? (e & 0x7fffffffu) : ~e;
    return __uint_as_float(u);
}

__global__ void init_min_kernel() { g_min_bits = 0xFFFFFFFFu; }

// ---------------- conversion kernels ----------------
__device__ __forceinline__ void split4(float4 x, __nv_bfloat16* h, __nv_bfloat16* l) {
    float v[4] = {x.x, x.y, x.z, x.w};
#pragma unroll
    for (int i = 0; i < 4; i++) {
        __nv_bfloat16 hi = __float2bfloat16_rn(v[i]);
        h[i] = hi;
        l[i] = __float2bfloat16_rn(v[i] - __bfloat162float(hi));
    }
}

__global__ void __launch_bounds__(256) conv_input_kernel(const float* __restrict__ inp) {
    size_t i = (size_t)blockIdx.x * 256 + threadIdx.x;   // float4 index
    float4 x = ((const float4*)inp)[i];
    __nv_bfloat16 h[4], l[4];
    split4(x, h, l);
#pragma unroll
    for (int j = 0; j < 4; j++) { g_Ah[i*4+j] = h[j]; g_Al[i*4+j] = l[j]; }
}

__global__ void __launch_bounds__(256) conv_w_kernel(WPtrs P) {
    int c = blockIdx.y;
    int n4 = (512 * c_cK[c]) >> 2;
    int i = blockIdx.x * 256 + threadIdx.x;
    if (i >= n4) return;
    float4 x = ((const float4*)P.w[c])[i];
    __nv_bfloat16 h[4], l[4];
    split4(x, h, l);
    size_t base = (size_t)c_cW[c] + (size_t)i * 4;
#pragma unroll
    for (int j = 0; j < 4; j++) { g_Wh[base+j] = h[j]; g_Wl[base+j] = l[j]; }
}

__global__ void __launch_bounds__(256) conv_fcw_kernel(const float* __restrict__ fcw) {
    int i = blockIdx.x * 256 + threadIdx.x;   // 65536 float4s
    float4 x = ((const float4*)fcw)[i];
    __nv_bfloat16 h[4], l[4];
    split4(x, h, l);
#pragma unroll
    for (int j = 0; j < 4; j++) { g_FWh[i*4+j] = h[j]; g_FWl[i*4+j] = l[j]; }
}

// ---------------- mma.sync GEMM configuration ----------------
// CTA tile 128x128, BK=32 bf16, 3-stage cp.async pipeline.
// smem stage: [Ah | Al | Bh | Bl], each 128 rows x 40 bf16 (pitch 80B, 64B data).
#define PKW    20                 // pitch in 32-bit words (40 bf16 = 80B)
#define BUFW   (128*PKW)          // words per buffer = 2560
#define STAGE_BYTES (4*128*80)    // 40960
#define NSTAGE 3
#define GEMM_SMEM (NSTAGE*STAGE_BYTES)   // 122880

// load one 4-buffer stage (A 128xBK from rowstrideA bytes; B 128xBK from rowstrideB)
__device__ __forceinline__ void load_stage_g(
    uint32_t sbase, int tid,
    const char* Ah, const char* Al, size_t strA,
    const char* Bh, const char* Bl, size_t strB, size_t kb)
{
#pragma unroll
    for (int j = 0; j < 2; j++) {                 // 512 chunks per buffer / 256 thr
        int q = tid + j * 256;
        int r = q >> 2, cc = q & 3;
        uint32_t so = (uint32_t)(r * 80 + cc * 16);
        size_t ga = (size_t)r * strA + kb + cc * 16;
        cpa16(sbase + so,          Ah + ga);
        cpa16(sbase + 10240 + so,  Al + ga);
        size_t gb = (size_t)r * strB + kb + cc * 16;
        cpa16(sbase + 20480 + so,  Bh + gb);
        cpa16(sbase + 30720 + so,  Bl + gb);
    }
    cpa_commit();
}

// compute one stage: 2 k16 steps, 3-term split
__device__ __forceinline__ void compute_stage(
    const uint32_t* sS, int wm, int wn, int lane, float acc[2][8][4])
{
    const uint32_t* sAh = sS;
    const uint32_t* sAl = sS + BUFW;
    const uint32_t* sBh = sS + 2*BUFW;
    const uint32_t* sBl = sS + 3*BUFW;
    const int l4 = lane >> 2, lm = lane & 3;

#pragma unroll
    for (int k16 = 0; k16 < 2; k16++) {
        uint32_t ah[2][4], al[2][4], bh[8][2], bl[8][2];
        const int ko = k16 * 8;
#pragma unroll
        for (int mt = 0; mt < 2; mt++) {
            int r0 = (wm*32 + mt*16 + l4) * PKW + lm + ko;
            int r1 = r0 + 8*PKW;
            ah[mt][0] = sAh[r0];     ah[mt][1] = sAh[r1];
            ah[mt][2] = sAh[r0 + 4]; ah[mt][3] = sAh[r1 + 4];
            al[mt][0] = sAl[r0];     al[mt][1] = sAl[r1];
            al[mt][2] = sAl[r0 + 4]; al[mt][3] = sAl[r1 + 4];
        }
#pragma unroll
        for (int nt = 0; nt < 8; nt++) {
            int b0 = (wn*64 + nt*8 + l4) * PKW + lm + ko;
            bh[nt][0] = sBh[b0]; bh[nt][1] = sBh[b0 + 4];
            bl[nt][0] = sBl[b0]; bl[nt][1] = sBl[b0 + 4];
        }
#pragma unroll
        for (int mt = 0; mt < 2; mt++)
#pragma unroll
            for (int nt = 0; nt < 8; nt++) mma16816(acc[mt][nt], ah[mt], bh[nt]);
#pragma unroll
        for (int mt = 0; mt < 2; mt++)
#pragma unroll
            for (int nt = 0; nt < 8; nt++) mma16816(acc[mt][nt], ah[mt], bl[nt]);
#pragma unroll
        for (int mt = 0; mt < 2; mt++)
#pragma unroll
            for (int nt = 0; nt < 8; nt++) mma16816(acc[mt][nt], al[mt], bh[nt]);
    }
}

// ---------------- QKV GEMM ----------------
// grid (4 ntiles, 128 mtiles, 18 combos), 256 threads.
__global__ void __launch_bounds__(256, 1)
qkv_mma_kernel()
{
    extern __shared__ char smem[];
    const uint32_t sb = smem_u32(smem);
    const int tid = threadIdx.x, wid = tid >> 5, lane = tid & 31;
    const int wm = wid & 3, wn = wid >> 2;
    const int n0 = blockIdx.x * 128;
    const int m0 = blockIdx.y * 128;
    const int c  = blockIdx.z;
    const int Kdim = c_cK[c];
    const int seg  = c_cOff[c];
    const int s = c / 3, w = c % 3;
    const int nc = Kdim >> 5;

    const char* Ah = (const char*)(g_Ah + (size_t)m0 * DIN + seg);
    const char* Al = (const char*)(g_Al + (size_t)m0 * DIN + seg);
    const char* Bh = (const char*)(g_Wh + (size_t)c_cW[c] + (size_t)n0 * Kdim);
    const char* Bl = (const char*)(g_Wl + (size_t)c_cW[c] + (size_t)n0 * Kdim);
    const size_t strA = (size_t)DIN * 2, strB = (size_t)Kdim * 2;

    float acc[2][8][4];
#pragma unroll
    for (int i = 0; i < 2; i++)
#pragma unroll
        for (int j = 0; j < 8; j++)
#pragma unroll
            for (int k = 0; k < 4; k++) acc[i][j][k] = 0.0f;

    load_stage_g(sb, tid, Ah, Al, strA, Bh, Bl, strB, 0);
    load_stage_g(sb + STAGE_BYTES, tid, Ah, Al, strA, Bh, Bl, strB, 64);

    for (int i = 0; i < nc; i++) {
        if (i < nc - 1) cpa_wait1(); else cpa_wait0();
        __syncthreads();
        if (i + 2 < nc)
            load_stage_g(sb + ((i+2) % 3) * STAGE_BYTES, tid,
                         Ah, Al, strA, Bh, Bl, strB, (size_t)(i+2) * 64);
        compute_stage((const uint32_t*)(smem + (i % 3) * STAGE_BYTES),
                      wm, wn, lane, acc);
    }
    __syncthreads();

    // epilogue: acc -> smem (128 x 132 fp32) -> coalesced global
    float* tb = (float*)smem;
    {
        const int l4 = lane >> 2, lm = lane & 3;
#pragma unroll
        for (int mt = 0; mt < 2; mt++)
#pragma unroll
            for (int nt = 0; nt < 8; nt++) {
                int R = wm*32 + mt*16 + l4;
                int C = wn*64 + nt*8 + lm*2;
                tb[R*132 + C]       = acc[mt][nt][0];
                tb[R*132 + C + 1]   = acc[mt][nt][1];
                tb[(R+8)*132 + C]   = acc[mt][nt][2];
                tb[(R+8)*132 + C+1] = acc[mt][nt][3];
            }
    }
    __syncthreads();
    float* Cb = (w == 0) ? g_Q : (w == 1) ? g_K : g_V;
#pragma unroll
    for (int it = 0; it < 16; it++) {
        int v = tid + it * 256;
        int rr = v >> 5, c4 = (v & 31) * 4;
        float4 o = make_float4(tb[rr*132 + c4], tb[rr*132 + c4 + 1],
                               tb[rr*132 + c4 + 2], tb[rr*132 + c4 + 3]);
        *(float4*)(Cb + ((size_t)(m0 + rr) * MSEG + s) * DM + n0 + c4) = o;
    }
}

// ---------------- FC GEMM + bias + residual ----------------
// grid (4 ntiles, 768 mtiles), 256 threads. C = AO(98304x512) @ fcw^T
__global__ void __launch_bounds__(256, 1)
fc_mma_kernel(const float* __restrict__ fcb, float* __restrict__ outp)
{
    extern __shared__ char smem[];
    const uint32_t sb = smem_u32(smem);
    const int tid = threadIdx.x, wid = tid >> 5, lane = tid & 31;
    const int wm = wid & 3, wn = wid >> 2;
    const int n0 = blockIdx.x * 128;
    const int m0 = blockIdx.y * 128;
    const int nc = 16;                       // K = 512

    const char* Ah = (const char*)(g_AOh + (size_t)m0 * DM);
    const char* Al = (const char*)(g_AOl + (size_t)m0 * DM);
    const char* Bh = (const char*)(g_FWh + (size_t)n0 * DM);
    const char* Bl = (const char*)(g_FWl + (size_t)n0 * DM);
    const size_t strA = (size_t)DM * 2, strB = (size_t)DM * 2;

    float acc[2][8][4];
#pragma unroll
    for (int i = 0; i < 2; i++)
#pragma unroll
        for (int j = 0; j < 8; j++)
#pragma unroll
            for (int k = 0; k < 4; k++) acc[i][j][k] = 0.0f;

    load_stage_g(sb, tid, Ah, Al, strA, Bh, Bl, strB, 0);
    load_stage_g(sb + STAGE_BYTES, tid, Ah, Al, strA, Bh, Bl, strB, 64);

    for (int i = 0; i < nc; i++) {
        if (i < nc - 1) cpa_wait1(); else cpa_wait0();
        __syncthreads();
        if (i + 2 < nc)
            load_stage_g(sb + ((i+2) % 3) * STAGE_BYTES, tid,
                         Ah, Al, strA, Bh, Bl, strB, (size_t)(i+2) * 64);
        compute_stage((const uint32_t*)(smem + (i % 3) * STAGE_BYTES),
                      wm, wn, lane, acc);
    }
    __syncthreads();

    float* tb = (float*)smem;
    {
        const int l4 = lane >> 2, lm = lane & 3;
#pragma unroll
        for (int mt = 0; mt < 2; mt++)
#pragma unroll
            for (int nt = 0; nt < 8; nt++) {
                int R = wm*32 + mt*16 + l4;
                int C = wn*64 + nt*8 + lm*2;
                tb[R*132 + C]       = acc[mt][nt][0];
                tb[R*132 + C + 1]   = acc[mt][nt][1];
                tb[(R+8)*132 + C]   = acc[mt][nt][2];
                tb[(R+8)*132 + C+1] = acc[mt][nt][3];
            }
    }
    __syncthreads();
#pragma unroll
    for (int it = 0; it < 16; it++) {
        int v = tid + it * 256;
        int rr = v >> 5, c4 = (v & 31) * 4;
        int m = m0 + rr, n = n0 + c4;
        float4 bb = *(const float4*)(fcb + n);
        float4 vv = *(const float4*)(g_V + (size_t)m * DM + n);
        float4 o;
        o.x = tb[rr*132 + c4]     + bb.x + vv.x;
        o.y = tb[rr*132 + c4 + 1] + bb.y + vv.y;
        o.z = tb[rr*132 + c4 + 2] + bb.z + vv.z;
        o.w = tb[rr*132 + c4 + 3] + bb.w + vv.w;
        *(float4*)(outp + (size_t)m * DM + n) = o;
    }
}

// ---------------- attention logits + global min ----------------
__global__ void __launch_bounds__(256)
attn_logits_kernel()
{
    const int b    = blockIdx.x;
    const int h    = threadIdx.x >> 5;
    const int lane = threadIdx.x & 31;

    const float* Qb = g_Q + (size_t)b * (MSEG*DM) + h * 64 + lane;
    const float* Kb = g_K + (size_t)b * (MSEG*DM) + h * 64 + lane;

    float q0[6], q1[6], k0v[6], k1v[6];
#pragma unroll
    for (int t = 0; t < 6; t++) {
        q0[t]  = Qb[t*DM];  q1[t]  = Qb[t*DM + 32];
        k0v[t] = Kb[t*DM];  k1v[t] = Kb[t*DM + 32];
    }

    float lmin = 3.4e38f;
    float* lp = g_logits + ((size_t)b * NH + h) * 36;
#pragma unroll
    for (int tq = 0; tq < 6; tq++) {
#pragma unroll
        for (int tk = 0; tk < 6; tk++) {
            float p = q0[tq]*k0v[tk] + q1[tq]*k1v[tk];
#pragma unroll
            for (int o = 16; o > 0; o >>= 1)
                p += __shfl_xor_sync(0xffffffffu, p, o);
            p *= INV_TEMP;
            if (lane == 0) {
                lp[tq*6 + tk] = p;
                lmin = fminf(lmin, p);
            }
        }
    }
    if (lane == 0) atomicMin(&g_min_bits, fenc(lmin));
}

// ---------------- finalize attention + attn@V (writes AO hi/lo bf16) ----------------
__global__ void __launch_bounds__(256)
attn_finalize_kernel(float* __restrict__ attn_out)
{
    const int b   = blockIdx.x;
    const int tid = threadIdx.x;
    __shared__ float at[NH*36];
    __shared__ float s_scale;

    if (tid == 0) s_scale = 1.0f / fabsf(fdec(g_min_bits));
    __syncthreads();
    const float scale = s_scale;

    if (tid < 48) {
        int h = tid / 6, tq = tid % 6;
        const float* lp = g_logits + ((size_t)b * NH + h) * 36 + tq * 6;
        float v[6]; float ss = 0.0f;
#pragma unroll
        for (int k = 0; k < 6; k++) { v[k] = lp[k] * scale; ss += v[k]*v[k]; }
        float inorm = 1.0f / fmaxf(sqrtf(ss), 1e-12f);
        float mx = -3.4e38f;
#pragma unroll
        for (int k = 0; k < 6; k++) { v[k] *= inorm; mx = fmaxf(mx, v[k]); }
        float es = 0.0f; float e[6];
#pragma unroll
        for (int k = 0; k < 6; k++) { e[k] = expf(v[k] - mx); es += e[k]; }
        float r = 1.0f / es;
        float* ao = attn_out + ((size_t)b * NH + h) * 36 + tq * 6;
#pragma unroll
        for (int k = 0; k < 6; k++) {
            float a = e[k] * r;
            at[h*36 + tq*6 + k] = a;
            ao[k] = a;
        }
    }
    __syncthreads();

    const float* Vb = g_V + (size_t)b * (MSEG*DM);
    size_t base = (size_t)b * (MSEG*DM);
    for (int idx = tid; idx < MSEG*DM; idx += 256) {
        int t = idx >> 9;
        int f = idx & 511;
        int h = f >> 6;
        const float* ar = &at[h*36 + t*6];
        float sv = 0.0f;
#pragma unroll
        for (int k = 0; k < 6; k++) sv += ar[k] * Vb[k*DM + f];
        __nv_bfloat16 hi = __float2bfloat16_rn(sv);
        g_AOh[base + idx] = hi;
        g_AOl[base + idx] = __float2bfloat16_rn(sv - __bfloat162float(hi));
    }
}

// ---------------- LayerNorm ----------------
__global__ void __launch_bounds__(128)
ln_kernel(float* __restrict__ outp, const float* __restrict__ g,
          const float* __restrict__ be)
{
    const int row = blockIdx.x;
    float* p = outp + (size_t)row * DM;
    const int tid = threadIdx.x;

    float4 x = *(const float4*)(p + tid * 4);
    float s  = x.x + x.y + x.z + x.w;
    float sq = x.x*x.x + x.y*x.y + x.z*x.z + x.w*x.w;

#pragma unroll
    for (int o = 16; o > 0; o >>= 1) {
        s  += __shfl_xor_sync(0xffffffffu, s,  o);
        sq += __shfl_xor_sync(0xffffffffu, sq, o);
    }
    __shared__ float ws[4], wq[4];
    int w = tid >> 5, lane = tid & 31;
    if (lane == 0) { ws[w] = s; wq[w] = sq; }
    __syncthreads();
    s  = ws[0] + ws[1] + ws[2] + ws[3];
    sq = wq[0] + wq[1] + wq[2] + wq[3];

    float mu  = s * (1.0f / DM);
    float var = sq * (1.0f / DM) - mu * mu;
    float rstd = rsqrtf(var + LN_EPS);

    int c = tid * 4;
    float4 gg = *(const float4*)(g + c);
    float4 bb = *(const float4*)(be + c);
    float4 o;
    o.x = (x.x - mu) * rstd * gg.x + bb.x;
    o.y = (x.y - mu) * rstd * gg.y + bb.y;
    o.z = (x.z - mu) * rstd * gg.z + bb.z;
    o.w = (x.w - mu) * rstd * gg.w + bb.w;
    *(float4*)(p + c) = o;
}

// ---------------- launch ----------------
extern "C" void kernel_launch(void* const* d_in, const int* in_sizes, int n_in,
                              void* d_out, int out_size)
{
    const float* inp = (const float*)d_in[0];
    WPtrs P;
    for (int i = 0; i < 18; i++) P.w[i] = (const float*)d_in[1 + i];
    const float* fc_w = (const float*)d_in[19];
    const float* fc_b = (const float*)d_in[20];
    const float* ln_g = (const float*)d_in[21];
    const float* ln_b = (const float*)d_in[22];

    float* outp     = (float*)d_out;
    float* attn_out = outp + (size_t)NROWS * DM;

    cudaFuncSetAttribute(qkv_mma_kernel, cudaFuncAttributeMaxDynamicSharedMemorySize, GEMM_SMEM);
    cudaFuncSetAttribute(fc_mma_kernel,  cudaFuncAttributeMaxDynamicSharedMemorySize, GEMM_SMEM);

    init_min_kernel<<<1, 1>>>();
    conv_input_kernel<<<(BS*(size_t)DIN/4 + 255)/256, 256>>>(inp);
    conv_w_kernel<<<dim3(1024, 18), 256>>>(P);
    conv_fcw_kernel<<<256, 256>>>(fc_w);
    qkv_mma_kernel<<<dim3(4, 128, 18), 256, GEMM_SMEM>>>();
    attn_logits_kernel<<<BS, 256>>>();
    attn_finalize_kernel<<<BS, 256>>>(attn_out);
    fc_mma_kernel<<<dim3(4, 768), 256, GEMM_SMEM>>>(fc_b, outp);
    ln_kernel<<<NROWS, 128>>>(outp, ln_g, ln_b);
}

// round 8
// speedup vs baseline: 2.6042x; 1.9513x over previous
#include <cuda_runtime.h>
#include <cuda_bf16.h>
#include <cstdint>

// ---------------- problem constants ----------------
#define BS     16384
#define MSEG   6
#define DM     512
#define NH     8
#define DIN    6144
#define NROWS  (BS*MSEG)            // 98304
#define QKV_ELEMS (NROWS*DM)        // 50331648
#define NLOGITS (BS*NH*36)
#define INV_TEMP 0.125f
#define LN_EPS 1e-6f
#define WPACK  9437184              // 512*6144*3

// ---------------- scratch ----------------
__device__ float g_Q[QKV_ELEMS];
__device__ float g_K[QKV_ELEMS];
__device__ float g_V[QKV_ELEMS];
__device__ float g_logits[NLOGITS];
__device__ unsigned g_min_bits;
__device__ __nv_bfloat16 g_Ah[(size_t)BS*DIN];
__device__ __nv_bfloat16 g_Al[(size_t)BS*DIN];
__device__ __nv_bfloat16 g_Wh[WPACK];
__device__ __nv_bfloat16 g_Wl[WPACK];
__device__ __nv_bfloat16 g_FWh[DM*DM];
__device__ __nv_bfloat16 g_FWl[DM*DM];
__device__ __nv_bfloat16 g_AOh[QKV_ELEMS];
__device__ __nv_bfloat16 g_AOl[QKV_ELEMS];

// combo c = s*3 + w  (w: 0=q, 1=k, 2=v)
__constant__ int c_cK[18]   = {2048,2048,2048,1024,1024,1024,512,512,512,
                               1536,1536,1536,768,768,768,256,256,256};
__constant__ int c_cOff[18] = {0,0,0,2048,2048,2048,3072,3072,3072,
                               3584,3584,3584,5120,5120,5120,5888,5888,5888};
__constant__ int c_cW[18]   = {0,1048576,2097152,3145728,3670016,4194304,
                               4718592,4980736,5242880,5505024,6291456,7077888,
                               7864320,8257536,8650752,9043968,9175040,9306112};

struct WPtrs { const float* w[18]; };

// ---------------- helpers ----------------
__device__ __forceinline__ uint32_t smem_u32(const void* p) {
    uint32_t a;
    asm("{ .reg .u64 t; cvta.to.shared.u64 t, %1; cvt.u32.u64 %0, t; }" : "=r"(a) : "l"(p));
    return a;
}
__device__ __forceinline__ void cpa16(uint32_t s, const void* g) {
    asm volatile("cp.async.cg.shared.global [%0], [%1], 16;" :: "r"(s), "l"(g));
}
__device__ __forceinline__ void cpa_commit() { asm volatile("cp.async.commit_group;" ::: "memory"); }
__device__ __forceinline__ void cpa_wait0()  { asm volatile("cp.async.wait_group 0;" ::: "memory"); }
__device__ __forceinline__ void cpa_wait1()  { asm volatile("cp.async.wait_group 1;" ::: "memory"); }

__device__ __forceinline__ void mma16816(float* c, const uint32_t* a, const uint32_t* b) {
    asm volatile(
        "mma.sync.aligned.m16n8k16.row.col.f32.bf16.bf16.f32 "
        "{%0,%1,%2,%3}, {%4,%5,%6,%7}, {%8,%9}, {%0,%1,%2,%3};"
        : "+f"(c[0]), "+f"(c[1]), "+f"(c[2]), "+f"(c[3])
        : "r"(a[0]), "r"(a[1]), "r"(a[2]), "r"(a[3]), "r"(b[0]), "r"(b[1]));
}
__device__ __forceinline__ void ldm_x4(uint32_t* r, uint32_t addr) {
    asm volatile("ldmatrix.sync.aligned.m8n8.x4.shared.b16 {%0,%1,%2,%3}, [%4];"
        : "=r"(r[0]), "=r"(r[1]), "=r"(r[2]), "=r"(r[3]) : "r"(addr));
}

// ---------------- min encoding ----------------
__device__ __forceinline__ unsigned fenc(float f) {
    unsigned u = __float_as_uint(f);
    return (u & 0x80000000u) ? ~u : (u | 0x80000000u);
}
__device__ __forceinline__ float fdec(unsigned e) {
    unsigned u = (e & 0x80000000u) ? (e & 0x7fffffffu) : ~e;
    return __uint_as_float(u);
}

// ---------------- conversion kernels ----------------
__device__ __forceinline__ void split4(float4 x, __nv_bfloat16* h, __nv_bfloat16* l) {
    float v[4] = {x.x, x.y, x.z, x.w};
#pragma unroll
    for (int i = 0; i < 4; i++) {
        __nv_bfloat16 hi = __float2bfloat16_rn(v[i]);
        h[i] = hi;
        l[i] = __float2bfloat16_rn(v[i] - __bfloat162float(hi));
    }
}

__global__ void __launch_bounds__(256) conv_input_kernel(const float* __restrict__ inp) {
    size_t i = (size_t)blockIdx.x * 256 + threadIdx.x;   // float4 index
    if (i == 0) g_min_bits = 0xFFFFFFFFu;
    float4 x = ((const float4*)inp)[i];
    __nv_bfloat16 h[4], l[4];
    split4(x, h, l);
#pragma unroll
    for (int j = 0; j < 4; j++) { g_Ah[i*4+j] = h[j]; g_Al[i*4+j] = l[j]; }
}

__global__ void __launch_bounds__(256) conv_w_kernel(WPtrs P) {
    int c = blockIdx.y;
    int n4 = (512 * c_cK[c]) >> 2;
    int i = blockIdx.x * 256 + threadIdx.x;
    if (i >= n4) return;
    float4 x = ((const float4*)P.w[c])[i];
    __nv_bfloat16 h[4], l[4];
    split4(x, h, l);
    size_t base = (size_t)c_cW[c] + (size_t)i * 4;
#pragma unroll
    for (int j = 0; j < 4; j++) { g_Wh[base+j] = h[j]; g_Wl[base+j] = l[j]; }
}

__global__ void __launch_bounds__(256) conv_fcw_kernel(const float* __restrict__ fcw) {
    int i = blockIdx.x * 256 + threadIdx.x;   // 65536 float4s
    float4 x = ((const float4*)fcw)[i];
    __nv_bfloat16 h[4], l[4];
    split4(x, h, l);
#pragma unroll
    for (int j = 0; j < 4; j++) { g_FWh[i*4+j] = h[j]; g_FWl[i*4+j] = l[j]; }
}

// ---------------- mma.sync GEMM configuration ----------------
// CTA tile 128x128, BK=32 bf16, 2-stage double buffer, 2 CTAs/SM.
// smem stage: [Ah | Al | Bh | Bl], each 128 rows x 40 bf16 (pitch 80B, 64B data).
#define STAGE_BYTES (4*128*80)    // 40960
#define GEMM_SMEM (2*STAGE_BYTES) // 81920

__device__ __forceinline__ void load_stage_g(
    uint32_t sbase, int tid,
    const char* Ah, const char* Al, size_t strA,
    const char* Bh, const char* Bl, size_t strB, size_t kb)
{
#pragma unroll
    for (int j = 0; j < 2; j++) {                 // 512 chunks per buffer / 256 thr
        int q = tid + j * 256;
        int r = q >> 2, cc = q & 3;
        uint32_t so = (uint32_t)(r * 80 + cc * 16);
        size_t ga = (size_t)r * strA + kb + cc * 16;
        cpa16(sbase + so,          Ah + ga);
        cpa16(sbase + 10240 + so,  Al + ga);
        size_t gb = (size_t)r * strB + kb + cc * 16;
        cpa16(sbase + 20480 + so,  Bh + gb);
        cpa16(sbase + 30720 + so,  Bl + gb);
    }
    cpa_commit();
}

// compute one stage via ldmatrix; aoff/boff are per-lane precomputed byte offsets
__device__ __forceinline__ void compute_stage(
    uint32_t sstage, uint32_t aoff, uint32_t boff, float acc[2][8][4])
{
    const uint32_t Ah_ = sstage,        Al_ = sstage + 10240;
    const uint32_t Bh_ = sstage + 20480, Bl_ = sstage + 30720;

#pragma unroll
    for (int k16 = 0; k16 < 2; k16++) {
        const uint32_t ko = k16 * 32;           // 8 words * 4B
        uint32_t ah[2][4], al[2][4];
#pragma unroll
        for (int mt = 0; mt < 2; mt++) {
            ldm_x4(ah[mt], Ah_ + aoff + mt * 1280 + ko);
            ldm_x4(al[mt], Al_ + aoff + mt * 1280 + ko);
        }
#pragma unroll
        for (int p = 0; p < 4; p++) {           // nt pairs
            uint32_t bh[4], bl[4];
            ldm_x4(bh, Bh_ + boff + p * 1280 + ko);
            ldm_x4(bl, Bl_ + boff + p * 1280 + ko);
#pragma unroll
            for (int mt = 0; mt < 2; mt++) {
                mma16816(acc[mt][2*p],   ah[mt], bh);
                mma16816(acc[mt][2*p+1], ah[mt], bh + 2);
                mma16816(acc[mt][2*p],   ah[mt], bl);
                mma16816(acc[mt][2*p+1], ah[mt], bl + 2);
                mma16816(acc[mt][2*p],   al[mt], bh);
                mma16816(acc[mt][2*p+1], al[mt], bh + 2);
            }
        }
    }
}

// per-lane ldmatrix offsets (bytes, relative to buffer base)
__device__ __forceinline__ void ldm_offsets(int wm, int wn, int lane,
                                            uint32_t& aoff, uint32_t& boff)
{
    int g = lane >> 3, r8 = lane & 7;
    // A 16x16 tiles: groups 0/1 -> rows +0/+8 (k lo), 2/3 -> rows +0/+8 (k hi)
    int arow = wm * 32 + r8 + (g & 1) * 8;
    int acolw = (g >> 1) * 4;
    aoff = (uint32_t)(arow * 80 + acolw * 4);
    // B nt-pair: groups 0/1 -> nt even (k lo / k hi), 2/3 -> nt odd
    int brow = wn * 64 + r8 + (g >> 1) * 8;
    int bcolw = (g & 1) * 4;
    boff = (uint32_t)(brow * 80 + bcolw * 4);
}

// ---------------- QKV GEMM ----------------
// grid (4 ntiles, 128 mtiles, 18 combos), 256 threads.
__global__ void __launch_bounds__(256, 2)
qkv_mma_kernel()
{
    extern __shared__ char smem[];
    const uint32_t sb = smem_u32(smem);
    const int tid = threadIdx.x, wid = tid >> 5, lane = tid & 31;
    const int wm = wid & 3, wn = wid >> 2;
    const int n0 = blockIdx.x * 128;
    const int m0 = blockIdx.y * 128;
    const int c  = blockIdx.z;
    const int Kdim = c_cK[c];
    const int seg  = c_cOff[c];
    const int s = c / 3, w = c % 3;
    const int nc = Kdim >> 5;

    const char* Ah = (const char*)(g_Ah + (size_t)m0 * DIN + seg);
    const char* Al = (const char*)(g_Al + (size_t)m0 * DIN + seg);
    const char* Bh = (const char*)(g_Wh + (size_t)c_cW[c] + (size_t)n0 * Kdim);
    const char* Bl = (const char*)(g_Wl + (size_t)c_cW[c] + (size_t)n0 * Kdim);
    const size_t strA = (size_t)DIN * 2, strB = (size_t)Kdim * 2;

    uint32_t aoff, boff;
    ldm_offsets(wm, wn, lane, aoff, boff);

    float acc[2][8][4];
#pragma unroll
    for (int i = 0; i < 2; i++)
#pragma unroll
        for (int j = 0; j < 8; j++)
#pragma unroll
            for (int k = 0; k < 4; k++) acc[i][j][k] = 0.0f;

    load_stage_g(sb, tid, Ah, Al, strA, Bh, Bl, strB, 0);

    for (int i = 0; i < nc; i++) {
        __syncthreads();                          // compute i-1 done by all warps
        if (i + 1 < nc) {
            load_stage_g(sb + ((i+1) & 1) * STAGE_BYTES, tid,
                         Ah, Al, strA, Bh, Bl, strB, (size_t)(i+1) * 64);
            cpa_wait1();
        } else {
            cpa_wait0();
        }
        __syncthreads();                          // stage i visible to all
        compute_stage(sb + (i & 1) * STAGE_BYTES, aoff, boff, acc);
    }
    __syncthreads();

    // epilogue: acc -> smem (128 x 132 fp32) -> coalesced global
    float* tb = (float*)smem;
    {
        const int l4 = lane >> 2, lm = lane & 3;
#pragma unroll
        for (int mt = 0; mt < 2; mt++)
#pragma unroll
            for (int nt = 0; nt < 8; nt++) {
                int R = wm*32 + mt*16 + l4;
                int C = wn*64 + nt*8 + lm*2;
                tb[R*132 + C]       = acc[mt][nt][0];
                tb[R*132 + C + 1]   = acc[mt][nt][1];
                tb[(R+8)*132 + C]   = acc[mt][nt][2];
                tb[(R+8)*132 + C+1] = acc[mt][nt][3];
            }
    }
    __syncthreads();
    float* Cb = (w == 0) ? g_Q : (w == 1) ? g_K : g_V;
#pragma unroll
    for (int it = 0; it < 16; it++) {
        int v = tid + it * 256;
        int rr = v >> 5, c4 = (v & 31) * 4;
        float4 o = make_float4(tb[rr*132 + c4], tb[rr*132 + c4 + 1],
                               tb[rr*132 + c4 + 2], tb[rr*132 + c4 + 3]);
        *(float4*)(Cb + ((size_t)(m0 + rr) * MSEG + s) * DM + n0 + c4) = o;
    }
}

// ---------------- FC GEMM + bias + residual ----------------
// grid (4 ntiles, 768 mtiles), 256 threads. C = AO(98304x512) @ fcw^T
__global__ void __launch_bounds__(256, 2)
fc_mma_kernel(const float* __restrict__ fcb, float* __restrict__ outp)
{
    extern __shared__ char smem[];
    const uint32_t sb = smem_u32(smem);
    const int tid = threadIdx.x, wid = tid >> 5, lane = tid & 31;
    const int wm = wid & 3, wn = wid >> 2;
    const int n0 = blockIdx.x * 128;
    const int m0 = blockIdx.y * 128;
    const int nc = 16;                       // K = 512

    const char* Ah = (const char*)(g_AOh + (size_t)m0 * DM);
    const char* Al = (const char*)(g_AOl + (size_t)m0 * DM);
    const char* Bh = (const char*)(g_FWh + (size_t)n0 * DM);
    const char* Bl = (const char*)(g_FWl + (size_t)n0 * DM);
    const size_t strA = (size_t)DM * 2, strB = (size_t)DM * 2;

    uint32_t aoff, boff;
    ldm_offsets(wm, wn, lane, aoff, boff);

    float acc[2][8][4];
#pragma unroll
    for (int i = 0; i < 2; i++)
#pragma unroll
        for (int j = 0; j < 8; j++)
#pragma unroll
            for (int k = 0; k < 4; k++) acc[i][j][k] = 0.0f;

    load_stage_g(sb, tid, Ah, Al, strA, Bh, Bl, strB, 0);

    for (int i = 0; i < nc; i++) {
        __syncthreads();
        if (i + 1 < nc) {
            load_stage_g(sb + ((i+1) & 1) * STAGE_BYTES, tid,
                         Ah, Al, strA, Bh, Bl, strB, (size_t)(i+1) * 64);
            cpa_wait1();
        } else {
            cpa_wait0();
        }
        __syncthreads();
        compute_stage(sb + (i & 1) * STAGE_BYTES, aoff, boff, acc);
    }
    __syncthreads();

    float* tb = (float*)smem;
    {
        const int l4 = lane >> 2, lm = lane & 3;
#pragma unroll
        for (int mt = 0; mt < 2; mt++)
#pragma unroll
            for (int nt = 0; nt < 8; nt++) {
                int R = wm*32 + mt*16 + l4;
                int C = wn*64 + nt*8 + lm*2;
                tb[R*132 + C]       = acc[mt][nt][0];
                tb[R*132 + C + 1]   = acc[mt][nt][1];
                tb[(R+8)*132 + C]   = acc[mt][nt][2];
                tb[(R+8)*132 + C+1] = acc[mt][nt][3];
            }
    }
    __syncthreads();
#pragma unroll
    for (int it = 0; it < 16; it++) {
        int v = tid + it * 256;
        int rr = v >> 5, c4 = (v & 31) * 4;
        int m = m0 + rr, n = n0 + c4;
        float4 bb = *(const float4*)(fcb + n);
        float4 vv = *(const float4*)(g_V + (size_t)m * DM + n);
        float4 o;
        o.x = tb[rr*132 + c4]     + bb.x + vv.x;
        o.y = tb[rr*132 + c4 + 1] + bb.y + vv.y;
        o.z = tb[rr*132 + c4 + 2] + bb.z + vv.z;
        o.w = tb[rr*132 + c4 + 3] + bb.w + vv.w;
        *(float4*)(outp + (size_t)m * DM + n) = o;
    }
}

// ---------------- attention logits + global min ----------------
__global__ void __launch_bounds__(256)
attn_logits_kernel()
{
    const int b    = blockIdx.x;
    const int h    = threadIdx.x >> 5;
    const int lane = threadIdx.x & 31;

    const float* Qb = g_Q + (size_t)b * (MSEG*DM) + h * 64 + lane;
    const float* Kb = g_K + (size_t)b * (MSEG*DM) + h * 64 + lane;

    float q0[6], q1[6], k0v[6], k1v[6];
#pragma unroll
    for (int t = 0; t < 6; t++) {
        q0[t]  = Qb[t*DM];  q1[t]  = Qb[t*DM + 32];
        k0v[t] = Kb[t*DM];  k1v[t] = Kb[t*DM + 32];
    }

    float lmin = 3.4e38f;
    float* lp = g_logits + ((size_t)b * NH + h) * 36;
#pragma unroll
    for (int tq = 0; tq < 6; tq++) {
#pragma unroll
        for (int tk = 0; tk < 6; tk++) {
            float p = q0[tq]*k0v[tk] + q1[tq]*k1v[tk];
#pragma unroll
            for (int o = 16; o > 0; o >>= 1)
                p += __shfl_xor_sync(0xffffffffu, p, o);
            p *= INV_TEMP;
            if (lane == 0) {
                lp[tq*6 + tk] = p;
                lmin = fminf(lmin, p);
            }
        }
    }
    if (lane == 0) atomicMin(&g_min_bits, fenc(lmin));
}

// ---------------- finalize attention + attn@V (writes AO hi/lo bf16) ----------------
__global__ void __launch_bounds__(256)
attn_finalize_kernel(float* __restrict__ attn_out)
{
    const int b   = blockIdx.x;
    const int tid = threadIdx.x;
    __shared__ float at[NH*36];
    __shared__ float s_scale;

    if (tid == 0) s_scale = 1.0f / fabsf(fdec(g_min_bits));
    __syncthreads();
    const float scale = s_scale;

    if (tid < 48) {
        int h = tid / 6, tq = tid % 6;
        const float* lp = g_logits + ((size_t)b * NH + h) * 36 + tq * 6;
        float v[6]; float ss = 0.0f;
#pragma unroll
        for (int k = 0; k < 6; k++) { v[k] = lp[k] * scale; ss += v[k]*v[k]; }
        float inorm = 1.0f / fmaxf(sqrtf(ss), 1e-12f);
        float mx = -3.4e38f;
#pragma unroll
        for (int k = 0; k < 6; k++) { v[k] *= inorm; mx = fmaxf(mx, v[k]); }
        float es = 0.0f; float e[6];
#pragma unroll
        for (int k = 0; k < 6; k++) { e[k] = expf(v[k] - mx); es += e[k]; }
        float r = 1.0f / es;
        float* ao = attn_out + ((size_t)b * NH + h) * 36 + tq * 6;
#pragma unroll
        for (int k = 0; k < 6; k++) {
            float a = e[k] * r;
            at[h*36 + tq*6 + k] = a;
            ao[k] = a;
        }
    }
    __syncthreads();

    const float* Vb = g_V + (size_t)b * (MSEG*DM);
    size_t base = (size_t)b * (MSEG*DM);
    for (int idx = tid; idx < MSEG*DM; idx += 256) {
        int t = idx >> 9;
        int f = idx & 511;
        int h = f >> 6;
        const float* ar = &at[h*36 + t*6];
        float sv = 0.0f;
#pragma unroll
        for (int k = 0; k < 6; k++) sv += ar[k] * Vb[k*DM + f];
        __nv_bfloat16 hi = __float2bfloat16_rn(sv);
        g_AOh[base + idx] = hi;
        g_AOl[base + idx] = __float2bfloat16_rn(sv - __bfloat162float(hi));
    }
}

// ---------------- LayerNorm ----------------
__global__ void __launch_bounds__(128)
ln_kernel(float* __restrict__ outp, const float* __restrict__ g,
          const float* __restrict__ be)
{
    const int row = blockIdx.x;
    float* p = outp + (size_t)row * DM;
    const int tid = threadIdx.x;

    float4 x = *(const float4*)(p + tid * 4);
    float s  = x.x + x.y + x.z + x.w;
    float sq = x.x*x.x + x.y*x.y + x.z*x.z + x.w*x.w;

#pragma unroll
    for (int o = 16; o > 0; o >>= 1) {
        s  += __shfl_xor_sync(0xffffffffu, s,  o);
        sq += __shfl_xor_sync(0xffffffffu, sq, o);
    }
    __shared__ float ws[4], wq[4];
    int w = tid >> 5, lane = tid & 31;
    if (lane == 0) { ws[w] = s; wq[w] = sq; }
    __syncthreads();
    s  = ws[0] + ws[1] + ws[2] + ws[3];
    sq = wq[0] + wq[1] + wq[2] + wq[3];

    float mu  = s * (1.0f / DM);
    float var = sq * (1.0f / DM) - mu * mu;
    float rstd = rsqrtf(var + LN_EPS);

    int c = tid * 4;
    float4 gg = *(const float4*)(g + c);
    float4 bb = *(const float4*)(be + c);
    float4 o;
    o.x = (x.x - mu) * rstd * gg.x + bb.x;
    o.y = (x.y - mu) * rstd * gg.y + bb.y;
    o.z = (x.z - mu) * rstd * gg.z + bb.z;
    o.w = (x.w - mu) * rstd * gg.w + bb.w;
    *(float4*)(p + c) = o;
}

// ---------------- launch ----------------
extern "C" void kernel_launch(void* const* d_in, const int* in_sizes, int n_in,
                              void* d_out, int out_size)
{
    const float* inp = (const float*)d_in[0];
    WPtrs P;
    for (int i = 0; i < 18; i++) P.w[i] = (const float*)d_in[1 + i];
    const float* fc_w = (const float*)d_in[19];
    const float* fc_b = (const float*)d_in[20];
    const float* ln_g = (const float*)d_in[21];
    const float* ln_b = (const float*)d_in[22];

    float* outp     = (float*)d_out;
    float* attn_out = outp + (size_t)NROWS * DM;

    cudaFuncSetAttribute(qkv_mma_kernel, cudaFuncAttributeMaxDynamicSharedMemorySize, GEMM_SMEM);
    cudaFuncSetAttribute(fc_mma_kernel,  cudaFuncAttributeMaxDynamicSharedMemorySize, GEMM_SMEM);

    conv_input_kernel<<<(BS*(size_t)DIN/4 + 255)/256, 256>>>(inp);
    conv_w_kernel<<<dim3(1024, 18), 256>>>(P);
    conv_fcw_kernel<<<256, 256>>>(fc_w);
    qkv_mma_kernel<<<dim3(4, 128, 18), 256, GEMM_SMEM>>>();
    attn_logits_kernel<<<BS, 256>>>();
    attn_finalize_kernel<<<BS, 256>>>(attn_out);
    fc_mma_kernel<<<dim3(4, 768), 256, GEMM_SMEM>>>(fc_b, outp);
    ln_kernel<<<NROWS, 128>>>(outp, ln_g, ln_b);
}